// round 4
// baseline (speedup 1.0000x reference)
#include <cuda_runtime.h>
#include <cuda_fp16.h>
#include <cstdint>

#define BATCH 16
#define HEADS 16
#define SEQ   256
#define D     32
#define QT    64            // query rows per CTA
#define KSTR  40            // halves per K/V/Q smem row (padded)
#define SSTR  264           // halves per score smem row (padded)

// smem halves: K 256*40 + V 256*40 + Q 64*40 + S 64*264 = 39936 halves = 79872 B
#define SMEM_BYTES 79872

__device__ __forceinline__ uint32_t pack_halves(__half lo, __half hi) {
    return (uint32_t)__half_as_ushort(lo) | ((uint32_t)__half_as_ushort(hi) << 16);
}

// Well-defined 32-bit fragment load from __half smem (aligned pair).
__device__ __forceinline__ uint32_t ld_frag(const __half* p) {
    __half2 h = *(const __half2*)(p);
    return pack_halves(__low2half(h), __high2half(h));
}

__device__ __forceinline__ void mma16816(float& c0, float& c1, float& c2, float& c3,
                                         uint32_t a0, uint32_t a1, uint32_t a2, uint32_t a3,
                                         uint32_t b0, uint32_t b1) {
    asm volatile(
        "mma.sync.aligned.m16n8k16.row.col.f32.f16.f16.f32 "
        "{%0,%1,%2,%3}, {%4,%5,%6,%7}, {%8,%9}, {%0,%1,%2,%3};\n"
        : "+f"(c0), "+f"(c1), "+f"(c2), "+f"(c3)
        : "r"(a0), "r"(a1), "r"(a2), "r"(a3), "r"(b0), "r"(b1));
}

__global__ __launch_bounds__(256, 2)
void attn_kernel(const float* __restrict__ gq_base,
                 const float* __restrict__ gk_base,
                 const float* __restrict__ gv_base,
                 float* __restrict__ gout_base) {
    extern __shared__ __half smem[];
    __half* Ks = smem;                    // [SEQ][KSTR]
    __half* Vs = Ks + SEQ * KSTR;         // [SEQ][KSTR]
    __half* Qs = Vs + SEQ * KSTR;         // [QT][KSTR]
    __half* Ss = Qs + QT * KSTR;          // [QT][SSTR]  scores, then probs (in place)

    const int bh  = blockIdx.y;
    const int q0  = blockIdx.x * QT;
    const int tid = threadIdx.x;

    const float* gq = gq_base + (size_t)bh * SEQ * D + (size_t)q0 * D;
    const float* gk = gk_base + (size_t)bh * SEQ * D;
    const float* gv = gv_base + (size_t)bh * SEQ * D;

    // ---- Load K, V (256x32 f32) and Q (64x32 f32), convert to fp16 smem ----
    // chunk c: row = c>>3, seg = c&7 (one float4 = 4 elements each)
    #pragma unroll
    for (int c = tid; c < SEQ * 8; c += 256) {
        int r = c >> 3, s = c & 7;
        float4 kv = ((const float4*)(gk + r * D))[s];
        float4 vv = ((const float4*)(gv + r * D))[s];
        *(__half2*)(Ks + r * KSTR + s * 4)     = __floats2half2_rn(kv.x, kv.y);
        *(__half2*)(Ks + r * KSTR + s * 4 + 2) = __floats2half2_rn(kv.z, kv.w);
        *(__half2*)(Vs + r * KSTR + s * 4)     = __floats2half2_rn(vv.x, vv.y);
        *(__half2*)(Vs + r * KSTR + s * 4 + 2) = __floats2half2_rn(vv.z, vv.w);
    }
    #pragma unroll
    for (int c = tid; c < QT * 8; c += 256) {
        int r = c >> 3, s = c & 7;
        float4 qv = ((const float4*)(gq + r * D))[s];
        *(__half2*)(Qs + r * KSTR + s * 4)     = __floats2half2_rn(qv.x, qv.y);
        *(__half2*)(Qs + r * KSTR + s * 4 + 2) = __floats2half2_rn(qv.z, qv.w);
    }
    __syncthreads();

    const int warp = tid >> 5;
    const int lane = tid & 31;
    const int gid  = lane >> 2;   // 0..7
    const int tig  = lane & 3;    // 0..3

    // =========== Phase 1: S = fp16( (QK^T fp32 accum) / scale ) ===========
    {
        const int rt   = warp & 3;     // row tile 0..3
        const int kh   = warp >> 2;    // key half 0..1
        const int rowA = rt * 16;

        uint32_t a[2][4];
        #pragma unroll
        for (int kc = 0; kc < 2; kc++) {
            int c0 = kc * 16 + tig * 2;
            a[kc][0] = ld_frag(Qs + (rowA + gid)     * KSTR + c0);
            a[kc][1] = ld_frag(Qs + (rowA + gid + 8) * KSTR + c0);
            a[kc][2] = ld_frag(Qs + (rowA + gid)     * KSTR + c0 + 8);
            a[kc][3] = ld_frag(Qs + (rowA + gid + 8) * KSTR + c0 + 8);
        }

        const float inv_scale = 1.0f / 5.656854249492381f;

        #pragma unroll
        for (int nt = 0; nt < 16; nt++) {
            const int n0 = kh * 128 + nt * 8;
            float c0 = 0.f, c1 = 0.f, c2 = 0.f, c3 = 0.f;
            #pragma unroll
            for (int kc = 0; kc < 2; kc++) {
                int d0 = kc * 16 + tig * 2;
                uint32_t b0 = ld_frag(Ks + (n0 + gid) * KSTR + d0);
                uint32_t b1 = ld_frag(Ks + (n0 + gid) * KSTR + d0 + 8);
                mma16816(c0, c1, c2, c3, a[kc][0], a[kc][1], a[kc][2], a[kc][3], b0, b1);
            }
            *(__half2*)(Ss + (rowA + gid)     * SSTR + n0 + tig * 2) =
                __floats2half2_rn(c0 * inv_scale, c1 * inv_scale);
            *(__half2*)(Ss + (rowA + gid + 8) * SSTR + n0 + tig * 2) =
                __floats2half2_rn(c2 * inv_scale, c3 * inv_scale);
        }
    }
    __syncthreads();

    // =========== Phase 2: fp32 softmax over 256 cols, in place ===========
    {
        const int row  = tid >> 2;   // 0..63
        const int quad = tid & 3;    // 0..3, 64 cols each
        __half* srow = Ss + row * SSTR + quad * 64;

        float mx = -1e30f;
        #pragma unroll
        for (int j = 0; j < 64; j += 2) {
            float2 f = __half22float2(*(const __half2*)(srow + j));
            mx = fmaxf(mx, fmaxf(f.x, f.y));
        }
        mx = fmaxf(mx, __shfl_xor_sync(0xffffffffu, mx, 1));
        mx = fmaxf(mx, __shfl_xor_sync(0xffffffffu, mx, 2));

        float sum = 0.f;
        #pragma unroll
        for (int j = 0; j < 64; j += 2) {
            float2 f = __half22float2(*(const __half2*)(srow + j));
            sum += __expf(f.x - mx) + __expf(f.y - mx);
        }
        sum += __shfl_xor_sync(0xffffffffu, sum, 1);
        sum += __shfl_xor_sync(0xffffffffu, sum, 2);
        const float inv = 1.f / sum;

        #pragma unroll
        for (int j = 0; j < 64; j += 2) {
            float2 f = __half22float2(*(const __half2*)(srow + j));
            *(__half2*)(srow + j) =
                __floats2half2_rn(__expf(f.x - mx) * inv, __expf(f.y - mx) * inv);
        }
    }
    __syncthreads();

    // =========== Phase 3: O = P @ V (fp32 accum) -> fp16 -> f32 out ===========
    {
        const int rt   = warp & 3;
        const int dh   = warp >> 2;      // 0..1 -> d cols dh*16..+16
        const int rowA = rt * 16;

        float c[2][4];
        #pragma unroll
        for (int t = 0; t < 2; t++)
            c[t][0] = c[t][1] = c[t][2] = c[t][3] = 0.f;

        #pragma unroll
        for (int kc = 0; kc < 16; kc++) {
            const int k0 = kc * 16;
            uint32_t a0 = ld_frag(Ss + (rowA + gid)     * SSTR + k0 + tig * 2);
            uint32_t a1 = ld_frag(Ss + (rowA + gid + 8) * SSTR + k0 + tig * 2);
            uint32_t a2 = ld_frag(Ss + (rowA + gid)     * SSTR + k0 + 8 + tig * 2);
            uint32_t a3 = ld_frag(Ss + (rowA + gid + 8) * SSTR + k0 + 8 + tig * 2);
            #pragma unroll
            for (int t = 0; t < 2; t++) {
                const int n0 = dh * 16 + t * 8;
                uint32_t b0 = pack_halves(Vs[(k0 + tig * 2)     * KSTR + n0 + gid],
                                          Vs[(k0 + tig * 2 + 1) * KSTR + n0 + gid]);
                uint32_t b1 = pack_halves(Vs[(k0 + tig * 2 + 8) * KSTR + n0 + gid],
                                          Vs[(k0 + tig * 2 + 9) * KSTR + n0 + gid]);
                mma16816(c[t][0], c[t][1], c[t][2], c[t][3], a0, a1, a2, a3, b0, b1);
            }
        }

        // Round accumulators to fp16 (reference output dtype), widen to f32.
        float* go = gout_base + (size_t)bh * SEQ * D + (size_t)(q0 + rowA) * D;
        #pragma unroll
        for (int t = 0; t < 2; t++) {
            const int n0 = dh * 16 + t * 8;
            float2 lo, hi;
            lo.x = __half2float(__float2half_rn(c[t][0]));
            lo.y = __half2float(__float2half_rn(c[t][1]));
            hi.x = __half2float(__float2half_rn(c[t][2]));
            hi.y = __half2float(__float2half_rn(c[t][3]));
            *(float2*)(go + (gid)     * D + n0 + tig * 2) = lo;
            *(float2*)(go + (gid + 8) * D + n0 + tig * 2) = hi;
        }
    }
}

extern "C" void kernel_launch(void* const* d_in, const int* in_sizes, int n_in,
                              void* d_out, int out_size) {
    const float* q = (const float*)d_in[0];
    const float* k = (const float*)d_in[1];
    const float* v = (const float*)d_in[2];
    float* out = (float*)d_out;

    cudaFuncSetAttribute(attn_kernel, cudaFuncAttributeMaxDynamicSharedMemorySize, SMEM_BYTES);

    dim3 grid(SEQ / QT, BATCH * HEADS);
    attn_kernel<<<grid, 256, SMEM_BYTES>>>(q, k, v, out);
}

// round 5
// speedup vs baseline: 1.3148x; 1.3148x over previous
#include <cuda_runtime.h>
#include <cuda_fp16.h>
#include <cstdint>

#define BATCH 16
#define HEADS 16
#define SEQ   256
#define D     32
#define QT    64            // query rows per CTA
#define KSTR  40            // halves per K/V/Q smem row (80B pitch, LDSM conflict-free)

// halves: Ks 256*40 + Vs 256*40 + Qs 64*40 = 23040 -> 46080 B, + 1024 B stats
#define SMEM_BYTES 47104

__device__ __forceinline__ uint32_t pack_halves(__half lo, __half hi) {
    return (uint32_t)__half_as_ushort(lo) | ((uint32_t)__half_as_ushort(hi) << 16);
}

__device__ __forceinline__ void ldsm_x4(uint32_t r[4], const __half* p) {
    uint32_t a = (uint32_t)__cvta_generic_to_shared(p);
    asm volatile("ldmatrix.sync.aligned.m8n8.x4.shared.b16 {%0,%1,%2,%3}, [%4];"
                 : "=r"(r[0]), "=r"(r[1]), "=r"(r[2]), "=r"(r[3]) : "r"(a));
}

__device__ __forceinline__ void ldsm_x4_t(uint32_t r[4], const __half* p) {
    uint32_t a = (uint32_t)__cvta_generic_to_shared(p);
    asm volatile("ldmatrix.sync.aligned.m8n8.x4.trans.shared.b16 {%0,%1,%2,%3}, [%4];"
                 : "=r"(r[0]), "=r"(r[1]), "=r"(r[2]), "=r"(r[3]) : "r"(a));
}

__device__ __forceinline__ void mma16816(float& c0, float& c1, float& c2, float& c3,
                                         uint32_t a0, uint32_t a1, uint32_t a2, uint32_t a3,
                                         uint32_t b0, uint32_t b1) {
    asm volatile(
        "mma.sync.aligned.m16n8k16.row.col.f32.f16.f16.f32 "
        "{%0,%1,%2,%3}, {%4,%5,%6,%7}, {%8,%9}, {%0,%1,%2,%3};\n"
        : "+f"(c0), "+f"(c1), "+f"(c2), "+f"(c3)
        : "r"(a0), "r"(a1), "r"(a2), "r"(a3), "r"(b0), "r"(b1));
}

__global__ __launch_bounds__(256, 2)
void attn_kernel(const float* __restrict__ gq_base,
                 const float* __restrict__ gk_base,
                 const float* __restrict__ gv_base,
                 float* __restrict__ gout_base) {
    extern __shared__ __half smem[];
    __half* Ks = smem;                    // [SEQ][KSTR]
    __half* Vs = Ks + SEQ * KSTR;         // [SEQ][KSTR]
    __half* Qs = Vs + SEQ * KSTR;         // [QT][KSTR]
    float*  stats = (float*)(Qs + QT * KSTR); // max[2][64] | sum[2][64]  (256 floats)
    float*  Ob = (float*)Ks;              // [64][34] partial O, aliased over dead Ks

    const int bh  = blockIdx.y;
    const int q0  = blockIdx.x * QT;
    const int tid = threadIdx.x;

    const float* gq = gq_base + (size_t)bh * SEQ * D + (size_t)q0 * D;
    const float* gk = gk_base + (size_t)bh * SEQ * D;
    const float* gv = gv_base + (size_t)bh * SEQ * D;

    // ---- Load K, V (256x32 f32) and Q (64x32 f32), convert to fp16 smem ----
    #pragma unroll
    for (int c = tid; c < SEQ * 8; c += 256) {
        int r = c >> 3, s = c & 7;
        float4 kv = ((const float4*)(gk + r * D))[s];
        float4 vv = ((const float4*)(gv + r * D))[s];
        *(__half2*)(Ks + r * KSTR + s * 4)     = __floats2half2_rn(kv.x, kv.y);
        *(__half2*)(Ks + r * KSTR + s * 4 + 2) = __floats2half2_rn(kv.z, kv.w);
        *(__half2*)(Vs + r * KSTR + s * 4)     = __floats2half2_rn(vv.x, vv.y);
        *(__half2*)(Vs + r * KSTR + s * 4 + 2) = __floats2half2_rn(vv.z, vv.w);
    }
    #pragma unroll
    for (int c = tid; c < QT * 8; c += 256) {
        int r = c >> 3, s = c & 7;
        float4 qv = ((const float4*)(gq + r * D))[s];
        *(__half2*)(Qs + r * KSTR + s * 4)     = __floats2half2_rn(qv.x, qv.y);
        *(__half2*)(Qs + r * KSTR + s * 4 + 2) = __floats2half2_rn(qv.z, qv.w);
    }
    __syncthreads();

    const int warp = tid >> 5;
    const int lane = tid & 31;
    const int gid  = lane >> 2;   // 0..7
    const int tig  = lane & 3;    // 0..3
    const int rt   = warp & 3;    // row tile (16 rows)
    const int kh   = warp >> 2;   // key half (128 cols)
    const int rowA = rt * 16;

    // ---- Q A-fragments via ldmatrix.x4 (one per 16-wide k-chunk) ----
    uint32_t aQ[2][4];
    #pragma unroll
    for (int kc = 0; kc < 2; kc++)
        ldsm_x4(aQ[kc], Qs + (rowA + (lane & 15)) * KSTR + kc * 16 + (lane >> 4) * 8);

    // ---- Phase 1: S (16x128 per warp) in registers, fp32 accum ----
    float s[16][4];
    #pragma unroll
    for (int g = 0; g < 16; g++) s[g][0] = s[g][1] = s[g][2] = s[g][3] = 0.f;

    #pragma unroll
    for (int g = 0; g < 16; g++) {
        uint32_t kb[4];  // M0..M3 = K[n0..n0+7][0..7 | 8..15 | 16..23 | 24..31]
        ldsm_x4(kb, Ks + (kh * 128 + g * 8 + (lane & 7)) * KSTR + (lane >> 3) * 8);
        mma16816(s[g][0], s[g][1], s[g][2], s[g][3],
                 aQ[0][0], aQ[0][1], aQ[0][2], aQ[0][3], kb[0], kb[1]);
        mma16816(s[g][0], s[g][1], s[g][2], s[g][3],
                 aQ[1][0], aQ[1][1], aQ[1][2], aQ[1][3], kb[2], kb[3]);
    }

    // scale + round to fp16 (identical math to the passing version)
    const float inv_scale = 1.0f / 5.656854249492381f;
    #pragma unroll
    for (int g = 0; g < 16; g++) {
        #pragma unroll
        for (int j = 0; j < 4; j++)
            s[g][j] = __half2float(__float2half_rn(s[g][j] * inv_scale));
    }

    // ---- Softmax (registers + warp shuffles + cross-warp stats) ----
    float mlo = -1e30f, mhi = -1e30f;
    #pragma unroll
    for (int g = 0; g < 16; g++) {
        mlo = fmaxf(mlo, fmaxf(s[g][0], s[g][1]));
        mhi = fmaxf(mhi, fmaxf(s[g][2], s[g][3]));
    }
    mlo = fmaxf(mlo, __shfl_xor_sync(0xffffffffu, mlo, 1));
    mlo = fmaxf(mlo, __shfl_xor_sync(0xffffffffu, mlo, 2));
    mhi = fmaxf(mhi, __shfl_xor_sync(0xffffffffu, mhi, 1));
    mhi = fmaxf(mhi, __shfl_xor_sync(0xffffffffu, mhi, 2));

    float slo = 0.f, shi = 0.f;
    #pragma unroll
    for (int g = 0; g < 16; g++) {
        s[g][0] = __expf(s[g][0] - mlo);  slo += s[g][0];
        s[g][1] = __expf(s[g][1] - mlo);  slo += s[g][1];
        s[g][2] = __expf(s[g][2] - mhi);  shi += s[g][2];
        s[g][3] = __expf(s[g][3] - mhi);  shi += s[g][3];
    }
    slo += __shfl_xor_sync(0xffffffffu, slo, 1);
    slo += __shfl_xor_sync(0xffffffffu, slo, 2);
    shi += __shfl_xor_sync(0xffffffffu, shi, 1);
    shi += __shfl_xor_sync(0xffffffffu, shi, 2);

    if (tig == 0) {
        stats[kh * 64 + rowA + gid]           = mlo;
        stats[128 + kh * 64 + rowA + gid]     = slo;
        stats[kh * 64 + rowA + gid + 8]       = mhi;
        stats[128 + kh * 64 + rowA + gid + 8] = shi;
    }
    __syncthreads();

    float scalelo, scalehi;
    {
        int r = rowA + gid;
        float m0 = stats[r], m1 = stats[64 + r];
        float gm = fmaxf(m0, m1);
        float tot = stats[128 + r] * __expf(m0 - gm) + stats[192 + r] * __expf(m1 - gm);
        scalelo = __expf(mlo - gm) / tot;

        int r2 = r + 8;
        float n0 = stats[r2], n1 = stats[64 + r2];
        float gm2 = fmaxf(n0, n1);
        float tot2 = stats[128 + r2] * __expf(n0 - gm2) + stats[192 + r2] * __expf(n1 - gm2);
        scalehi = __expf(mhi - gm2) / tot2;
    }

    // ---- Phase 3: O_partial = P @ V over this warp's 128 keys ----
    float o[4][4];
    #pragma unroll
    for (int nt = 0; nt < 4; nt++) o[nt][0] = o[nt][1] = o[nt][2] = o[nt][3] = 0.f;

    #pragma unroll
    for (int kc = 0; kc < 8; kc++) {
        // P A-fragments straight from the S accumulator layout
        uint32_t a0 = pack_halves(__float2half_rn(s[2*kc][0] * scalelo),
                                  __float2half_rn(s[2*kc][1] * scalelo));
        uint32_t a1 = pack_halves(__float2half_rn(s[2*kc][2] * scalehi),
                                  __float2half_rn(s[2*kc][3] * scalehi));
        uint32_t a2 = pack_halves(__float2half_rn(s[2*kc+1][0] * scalelo),
                                  __float2half_rn(s[2*kc+1][1] * scalelo));
        uint32_t a3 = pack_halves(__float2half_rn(s[2*kc+1][2] * scalehi),
                                  __float2half_rn(s[2*kc+1][3] * scalehi));

        const __half* vbase = Vs + (kh * 128 + kc * 16 + (lane & 15)) * KSTR
                                 + ((lane >> 4) & 1) * 8;
        uint32_t vb[4];   // cols 0-15: M0/M1 = nt0 b0/b1, M2/M3 = nt1
        ldsm_x4_t(vb, vbase);
        mma16816(o[0][0], o[0][1], o[0][2], o[0][3], a0, a1, a2, a3, vb[0], vb[1]);
        mma16816(o[1][0], o[1][1], o[1][2], o[1][3], a0, a1, a2, a3, vb[2], vb[3]);

        uint32_t vb2[4];  // cols 16-31
        ldsm_x4_t(vb2, vbase + 16);
        mma16816(o[2][0], o[2][1], o[2][2], o[2][3], a0, a1, a2, a3, vb2[0], vb2[1]);
        mma16816(o[3][0], o[3][1], o[3][2], o[3][3], a0, a1, a2, a3, vb2[2], vb2[3]);
    }

    // ---- Combine the two key-halves, emit ----
    if (kh == 1) {
        #pragma unroll
        for (int nt = 0; nt < 4; nt++) {
            int c = nt * 8 + tig * 2;
            *(float2*)&Ob[(rowA + gid) * 34 + c]     = make_float2(o[nt][0], o[nt][1]);
            *(float2*)&Ob[(rowA + gid + 8) * 34 + c] = make_float2(o[nt][2], o[nt][3]);
        }
    }
    __syncthreads();
    if (kh == 0) {
        float* go = gout_base + (size_t)bh * SEQ * D + (size_t)(q0 + rowA) * D;
        #pragma unroll
        for (int nt = 0; nt < 4; nt++) {
            int c = nt * 8 + tig * 2;
            float2 plo = *(const float2*)&Ob[(rowA + gid) * 34 + c];
            float2 phi = *(const float2*)&Ob[(rowA + gid + 8) * 34 + c];
            float2 lo, hi;
            lo.x = __half2float(__float2half_rn(o[nt][0] + plo.x));
            lo.y = __half2float(__float2half_rn(o[nt][1] + plo.y));
            hi.x = __half2float(__float2half_rn(o[nt][2] + phi.x));
            hi.y = __half2float(__float2half_rn(o[nt][3] + phi.y));
            *(float2*)(go + (gid)     * D + c) = lo;
            *(float2*)(go + (gid + 8) * D + c) = hi;
        }
    }
}

extern "C" void kernel_launch(void* const* d_in, const int* in_sizes, int n_in,
                              void* d_out, int out_size) {
    const float* q = (const float*)d_in[0];
    const float* k = (const float*)d_in[1];
    const float* v = (const float*)d_in[2];
    float* out = (float*)d_out;

    dim3 grid(SEQ / QT, BATCH * HEADS);
    attn_kernel<<<grid, 256, SMEM_BYTES>>>(q, k, v, out);
}

// round 6
// speedup vs baseline: 1.3165x; 1.0013x over previous
#include <cuda_runtime.h>
#include <cuda_fp16.h>
#include <cstdint>

#define BATCH 16
#define HEADS 16
#define SEQ   256
#define D     32
#define QT    64            // query rows per CTA
#define KSTR  40            // halves per K/V/Q smem row (80B pitch, LDSM conflict-free)

// halves: Ks 256*40 + Vs 256*40 + Qs 64*40 = 23040 -> 46080 B, + 1024 B stats
#define SMEM_BYTES 47104

__device__ __forceinline__ uint32_t pack_halves(__half lo, __half hi) {
    return (uint32_t)__half_as_ushort(lo) | ((uint32_t)__half_as_ushort(hi) << 16);
}

// __half2 -> uint32 register view (folds to a no-op move after F2FP.PACK)
__device__ __forceinline__ uint32_t h2u(__half2 h) {
    return pack_halves(__low2half(h), __high2half(h));
}

__device__ __forceinline__ void ldsm_x4(uint32_t r[4], const __half* p) {
    uint32_t a = (uint32_t)__cvta_generic_to_shared(p);
    asm volatile("ldmatrix.sync.aligned.m8n8.x4.shared.b16 {%0,%1,%2,%3}, [%4];"
                 : "=r"(r[0]), "=r"(r[1]), "=r"(r[2]), "=r"(r[3]) : "r"(a));
}

__device__ __forceinline__ void ldsm_x4_t(uint32_t r[4], const __half* p) {
    uint32_t a = (uint32_t)__cvta_generic_to_shared(p);
    asm volatile("ldmatrix.sync.aligned.m8n8.x4.trans.shared.b16 {%0,%1,%2,%3}, [%4];"
                 : "=r"(r[0]), "=r"(r[1]), "=r"(r[2]), "=r"(r[3]) : "r"(a));
}

__device__ __forceinline__ void mma16816(float& c0, float& c1, float& c2, float& c3,
                                         uint32_t a0, uint32_t a1, uint32_t a2, uint32_t a3,
                                         uint32_t b0, uint32_t b1) {
    asm volatile(
        "mma.sync.aligned.m16n8k16.row.col.f32.f16.f16.f32 "
        "{%0,%1,%2,%3}, {%4,%5,%6,%7}, {%8,%9}, {%0,%1,%2,%3};\n"
        : "+f"(c0), "+f"(c1), "+f"(c2), "+f"(c3)
        : "r"(a0), "r"(a1), "r"(a2), "r"(a3), "r"(b0), "r"(b1));
}

__global__ __launch_bounds__(256, 2)
void attn_kernel(const float* __restrict__ gq_base,
                 const float* __restrict__ gk_base,
                 const float* __restrict__ gv_base,
                 float* __restrict__ gout_base) {
    extern __shared__ __half smem[];
    __half* Ks = smem;                    // [SEQ][KSTR]
    __half* Vs = Ks + SEQ * KSTR;         // [SEQ][KSTR]
    __half* Qs = Vs + SEQ * KSTR;         // [QT][KSTR]
    float*  stats = (float*)(Qs + QT * KSTR); // max[2][64] | sum[2][64]  (256 floats)
    float*  Ob = (float*)Ks;              // [64][34] partial O, aliased over dead Ks

    const int bh  = blockIdx.y;
    const int q0  = blockIdx.x * QT;
    const int tid = threadIdx.x;

    const float* gq = gq_base + (size_t)bh * SEQ * D + (size_t)q0 * D;
    const float* gk = gk_base + (size_t)bh * SEQ * D;
    const float* gv = gv_base + (size_t)bh * SEQ * D;

    // ---- Load K, V (256x32 f32) and Q (64x32 f32), convert to fp16 smem ----
    #pragma unroll
    for (int c = tid; c < SEQ * 8; c += 256) {
        int r = c >> 3, s = c & 7;
        float4 kv = ((const float4*)(gk + r * D))[s];
        float4 vv = ((const float4*)(gv + r * D))[s];
        uint2 kp = make_uint2(h2u(__floats2half2_rn(kv.x, kv.y)),
                              h2u(__floats2half2_rn(kv.z, kv.w)));
        uint2 vp = make_uint2(h2u(__floats2half2_rn(vv.x, vv.y)),
                              h2u(__floats2half2_rn(vv.z, vv.w)));
        *(uint2*)(Ks + r * KSTR + s * 4) = kp;
        *(uint2*)(Vs + r * KSTR + s * 4) = vp;
    }
    #pragma unroll
    for (int c = tid; c < QT * 8; c += 256) {
        int r = c >> 3, s = c & 7;
        float4 qv = ((const float4*)(gq + r * D))[s];
        uint2 qp = make_uint2(h2u(__floats2half2_rn(qv.x, qv.y)),
                              h2u(__floats2half2_rn(qv.z, qv.w)));
        *(uint2*)(Qs + r * KSTR + s * 4) = qp;
    }
    __syncthreads();

    const int warp = tid >> 5;
    const int lane = tid & 31;
    const int gid  = lane >> 2;   // 0..7
    const int tig  = lane & 3;    // 0..3
    const int rt   = warp & 3;    // row tile (16 rows)
    const int kh   = warp >> 2;   // key half (128 cols)
    const int rowA = rt * 16;

    // ---- Q A-fragments via ldmatrix.x4 (one per 16-wide k-chunk) ----
    uint32_t aQ[2][4];
    #pragma unroll
    for (int kc = 0; kc < 2; kc++)
        ldsm_x4(aQ[kc], Qs + (rowA + (lane & 15)) * KSTR + kc * 16 + (lane >> 4) * 8);

    // ---- Phase 1: S (16x128 per warp) in registers, fp32 accum ----
    float s[16][4];
    #pragma unroll
    for (int g = 0; g < 16; g++) s[g][0] = s[g][1] = s[g][2] = s[g][3] = 0.f;

    #pragma unroll
    for (int g = 0; g < 16; g++) {
        uint32_t kb[4];  // M0..M3 = K[n0..n0+7][0..7 | 8..15 | 16..23 | 24..31]
        ldsm_x4(kb, Ks + (kh * 128 + g * 8 + (lane & 7)) * KSTR + (lane >> 3) * 8);
        mma16816(s[g][0], s[g][1], s[g][2], s[g][3],
                 aQ[0][0], aQ[0][1], aQ[0][2], aQ[0][3], kb[0], kb[1]);
        mma16816(s[g][0], s[g][1], s[g][2], s[g][3],
                 aQ[1][0], aQ[1][1], aQ[1][2], aQ[1][3], kb[2], kb[3]);
    }

    // scale + round to fp16 (packed, same RN rounding -> identical numerics)
    const float inv_scale = 1.0f / 5.656854249492381f;
    #pragma unroll
    for (int g = 0; g < 16; g++) {
        float2 f01 = __half22float2(__floats2half2_rn(s[g][0] * inv_scale,
                                                      s[g][1] * inv_scale));
        float2 f23 = __half22float2(__floats2half2_rn(s[g][2] * inv_scale,
                                                      s[g][3] * inv_scale));
        s[g][0] = f01.x; s[g][1] = f01.y; s[g][2] = f23.x; s[g][3] = f23.y;
    }

    // ---- Softmax (registers + warp shuffles + cross-warp stats) ----
    float mlo = -1e30f, mhi = -1e30f;
    #pragma unroll
    for (int g = 0; g < 16; g++) {
        mlo = fmaxf(mlo, fmaxf(s[g][0], s[g][1]));
        mhi = fmaxf(mhi, fmaxf(s[g][2], s[g][3]));
    }
    mlo = fmaxf(mlo, __shfl_xor_sync(0xffffffffu, mlo, 1));
    mlo = fmaxf(mlo, __shfl_xor_sync(0xffffffffu, mlo, 2));
    mhi = fmaxf(mhi, __shfl_xor_sync(0xffffffffu, mhi, 1));
    mhi = fmaxf(mhi, __shfl_xor_sync(0xffffffffu, mhi, 2));

    float slo = 0.f, shi = 0.f;
    #pragma unroll
    for (int g = 0; g < 16; g++) {
        s[g][0] = __expf(s[g][0] - mlo);  slo += s[g][0];
        s[g][1] = __expf(s[g][1] - mlo);  slo += s[g][1];
        s[g][2] = __expf(s[g][2] - mhi);  shi += s[g][2];
        s[g][3] = __expf(s[g][3] - mhi);  shi += s[g][3];
    }
    slo += __shfl_xor_sync(0xffffffffu, slo, 1);
    slo += __shfl_xor_sync(0xffffffffu, slo, 2);
    shi += __shfl_xor_sync(0xffffffffu, shi, 1);
    shi += __shfl_xor_sync(0xffffffffu, shi, 2);

    if (tig == 0) {
        stats[kh * 64 + rowA + gid]           = mlo;
        stats[128 + kh * 64 + rowA + gid]     = slo;
        stats[kh * 64 + rowA + gid + 8]       = mhi;
        stats[128 + kh * 64 + rowA + gid + 8] = shi;
    }
    __syncthreads();

    float scalelo, scalehi;
    {
        int r = rowA + gid;
        float m0 = stats[r], m1 = stats[64 + r];
        float gm = fmaxf(m0, m1);
        float tot = stats[128 + r] * __expf(m0 - gm) + stats[192 + r] * __expf(m1 - gm);
        scalelo = __expf(mlo - gm) / tot;

        int r2 = r + 8;
        float n0 = stats[r2], n1 = stats[64 + r2];
        float gm2 = fmaxf(n0, n1);
        float tot2 = stats[128 + r2] * __expf(n0 - gm2) + stats[192 + r2] * __expf(n1 - gm2);
        scalehi = __expf(mhi - gm2) / tot2;
    }

    // ---- Phase 3: O_partial = P @ V over this warp's 128 keys ----
    float o[4][4];
    #pragma unroll
    for (int nt = 0; nt < 4; nt++) o[nt][0] = o[nt][1] = o[nt][2] = o[nt][3] = 0.f;

    #pragma unroll
    for (int kc = 0; kc < 8; kc++) {
        // P A-fragments: fused scale + packed fp16 round (single RN round, as before)
        uint32_t a0 = h2u(__floats2half2_rn(s[2*kc][0]   * scalelo, s[2*kc][1]   * scalelo));
        uint32_t a1 = h2u(__floats2half2_rn(s[2*kc][2]   * scalehi, s[2*kc][3]   * scalehi));
        uint32_t a2 = h2u(__floats2half2_rn(s[2*kc+1][0] * scalelo, s[2*kc+1][1] * scalelo));
        uint32_t a3 = h2u(__floats2half2_rn(s[2*kc+1][2] * scalehi, s[2*kc+1][3] * scalehi));

        const __half* vbase = Vs + (kh * 128 + kc * 16 + (lane & 15)) * KSTR
                                 + ((lane >> 4) & 1) * 8;
        uint32_t vb[4];   // cols 0-15: M0/M1 = nt0 b0/b1, M2/M3 = nt1
        ldsm_x4_t(vb, vbase);
        mma16816(o[0][0], o[0][1], o[0][2], o[0][3], a0, a1, a2, a3, vb[0], vb[1]);
        mma16816(o[1][0], o[1][1], o[1][2], o[1][3], a0, a1, a2, a3, vb[2], vb[3]);

        uint32_t vb2[4];  // cols 16-31
        ldsm_x4_t(vb2, vbase + 16);
        mma16816(o[2][0], o[2][1], o[2][2], o[2][3], a0, a1, a2, a3, vb2[0], vb2[1]);
        mma16816(o[3][0], o[3][1], o[3][2], o[3][3], a0, a1, a2, a3, vb2[2], vb2[3]);
    }

    // ---- Combine the two key-halves, emit ----
    if (kh == 1) {
        #pragma unroll
        for (int nt = 0; nt < 4; nt++) {
            int c = nt * 8 + tig * 2;
            *(float2*)&Ob[(rowA + gid) * 34 + c]     = make_float2(o[nt][0], o[nt][1]);
            *(float2*)&Ob[(rowA + gid + 8) * 34 + c] = make_float2(o[nt][2], o[nt][3]);
        }
    }
    __syncthreads();
    if (kh == 0) {
        float* go = gout_base + (size_t)bh * SEQ * D + (size_t)(q0 + rowA) * D;
        #pragma unroll
        for (int nt = 0; nt < 4; nt++) {
            int c = nt * 8 + tig * 2;
            float2 plo = *(const float2*)&Ob[(rowA + gid) * 34 + c];
            float2 phi = *(const float2*)&Ob[(rowA + gid + 8) * 34 + c];
            float2 lo = __half22float2(__floats2half2_rn(o[nt][0] + plo.x, o[nt][1] + plo.y));
            float2 hi = __half22float2(__floats2half2_rn(o[nt][2] + phi.x, o[nt][3] + phi.y));
            *(float2*)(go + (gid)     * D + c) = lo;
            *(float2*)(go + (gid + 8) * D + c) = hi;
        }
    }
}

extern "C" void kernel_launch(void* const* d_in, const int* in_sizes, int n_in,
                              void* d_out, int out_size) {
    const float* q = (const float*)d_in[0];
    const float* k = (const float*)d_in[1];
    const float* v = (const float*)d_in[2];
    float* out = (float*)d_out;

    dim3 grid(SEQ / QT, BATCH * HEADS);
    attn_kernel<<<grid, 256, SMEM_BYTES>>>(q, k, v, out);
}